// round 15
// baseline (speedup 1.0000x reference)
#include <cuda_runtime.h>
#include <cuda_bf16.h>
#include <cuda_fp16.h>
#include <math.h>
#include <stdint.h>

// Problem constants
#define S_LEN 2048
#define BATCH 2
#define DMODEL 2048
#define NH 16
#define NKV 4
#define HD 128
#define SB (S_LEN*BATCH)
#define QW (NH*HD)
#define KW (NKV*HD)
#define KP_TOT 1024              // 2048 k / 2 per pair

// Scratch
__device__ float g_q[SB*QW];
__device__ float g_k[SB*KW];
__device__ float g_v[SB*KW];
// fp16-packed operands
__device__ uint32_t g_xP [SB*KP_TOT];
__device__ uint32_t g_oP [SB*KP_TOT];
__device__ uint32_t g_WqT[2048*KP_TOT];
__device__ uint32_t g_WkT[ 512*KP_TOT];
__device__ uint32_t g_WvT[ 512*KP_TOT];
__device__ uint32_t g_WoT[2048*KP_TOT];

// ---------------------------------------------------------------------------
// helpers
// ---------------------------------------------------------------------------
__device__ __forceinline__ void splitb(float x, __nv_bfloat16& h, __nv_bfloat16& l) {
    h = __float2bfloat16(x);
    l = __float2bfloat16(x - __bfloat162float(h));
}
__device__ __forceinline__ uint32_t packb(__nv_bfloat16 lo_k, __nv_bfloat16 hi_k) {
    __nv_bfloat162 p = __halves2bfloat162(lo_k, hi_k);
    return *(uint32_t*)&p;
}
__device__ __forceinline__ uint32_t packh(float a, float b) {
    __half2 h = __floats2half2_rn(a, b);   // .x = a (low bits) = even k
    return *(uint32_t*)&h;
}

__device__ __forceinline__ void mma_bf16(float* c,
    uint32_t a0, uint32_t a1, uint32_t a2, uint32_t a3,
    uint32_t b0, uint32_t b1)
{
    asm volatile(
        "mma.sync.aligned.m16n8k16.row.col.f32.bf16.bf16.f32 "
        "{%0,%1,%2,%3}, {%4,%5,%6,%7}, {%8,%9}, {%0,%1,%2,%3};"
        : "+f"(c[0]), "+f"(c[1]), "+f"(c[2]), "+f"(c[3])
        : "r"(a0), "r"(a1), "r"(a2), "r"(a3), "r"(b0), "r"(b1));
}
__device__ __forceinline__ void mma_fp16(float* c,
    uint32_t a0, uint32_t a1, uint32_t a2, uint32_t a3,
    uint32_t b0, uint32_t b1)
{
    asm volatile(
        "mma.sync.aligned.m16n8k16.row.col.f32.f16.f16.f32 "
        "{%0,%1,%2,%3}, {%4,%5,%6,%7}, {%8,%9}, {%0,%1,%2,%3};"
        : "+f"(c[0]), "+f"(c[1]), "+f"(c[2]), "+f"(c[3])
        : "r"(a0), "r"(a1), "r"(a2), "r"(a3), "r"(b0), "r"(b1));
}

// ---------------------------------------------------------------------------
// prep kernels
// ---------------------------------------------------------------------------
__global__ void __launch_bounds__(256) pack_h2(
    const float* __restrict__ src, uint32_t* __restrict__ dst, int n4)
{
    int i = blockIdx.x * 256 + threadIdx.x;
    if (i >= n4) return;
    float4 v = ((const float4*)src)[i];
    ((uint2*)dst)[i] = make_uint2(packh(v.x, v.y), packh(v.z, v.w));
}

__global__ void __launch_bounds__(256) transpose_pack(
    const float* __restrict__ W, uint32_t* __restrict__ WT, int N)
{
    __shared__ float sm[64][68];
    const int n0 = blockIdx.x * 64;
    const int k0 = blockIdx.y * 64;
    const int tid = threadIdx.x;
#pragma unroll
    for (int i = 0; i < 4; i++) {
        int idx = tid + i * 256;
        int kr = idx >> 4;
        int nq = idx & 15;
        float4 v = *(const float4*)&W[(size_t)(k0 + kr) * N + n0 + nq * 4];
        sm[kr][nq * 4 + 0] = v.x;
        sm[kr][nq * 4 + 1] = v.y;
        sm[kr][nq * 4 + 2] = v.z;
        sm[kr][nq * 4 + 3] = v.w;
    }
    __syncthreads();
    const int kp = tid & 31;
    const int nb = tid >> 5;
#pragma unroll
    for (int ph = 0; ph < 8; ph++) {
        int n = nb + ph * 8;
        WT[(size_t)(n0 + n) * KP_TOT + (k0 >> 1) + kp] =
            packh(sm[2 * kp][n], sm[2 * kp + 1][n]);
    }
}

// ---------------------------------------------------------------------------
// fp16 tensor-core GEMM tile (round-11 validated)
// ---------------------------------------------------------------------------
#define FSTR 36

__device__ __forceinline__ void gemm_fp16_tile(
    const uint32_t* __restrict__ Ap, const uint32_t* __restrict__ Bp,
    float* __restrict__ C, int ldc, int m0, int n0)
{
    __shared__ uint32_t As[128][FSTR];
    __shared__ uint32_t Bs[128][FSTR];

    const int tid  = threadIdx.x;
    const int lane = tid & 31;
    const int wid  = tid >> 5;
    const int wm   = wid >> 2;
    const int wn   = wid & 3;
    const int g    = lane >> 2;
    const int t    = lane & 3;

    float acc[4][4][4];
#pragma unroll
    for (int mm = 0; mm < 4; mm++)
#pragma unroll
        for (int nn = 0; nn < 4; nn++)
#pragma unroll
            for (int i = 0; i < 4; i++) acc[mm][nn][i] = 0.0f;

    uint4 pa[2], pb[2];
#pragma unroll
    for (int i = 0; i < 2; i++) {
        int idx = tid + i * 256;
        int r = idx >> 2, u = idx & 3;
        pa[i] = *(const uint4*)&Ap[(size_t)(m0 + r) * KP_TOT + u * 4];
        pb[i] = *(const uint4*)&Bp[(size_t)(n0 + r) * KP_TOT + u * 4];
    }

    for (int kt = 0; kt < 64; kt++) {
#pragma unroll
        for (int i = 0; i < 2; i++) {
            int idx = tid + i * 256;
            int r = idx >> 2, u = idx & 3;
            *(uint4*)&As[r][u * 4] = pa[i];
            *(uint4*)&Bs[r][u * 4] = pb[i];
        }
        __syncthreads();

        if (kt + 1 < 64) {
#pragma unroll
            for (int i = 0; i < 2; i++) {
                int idx = tid + i * 256;
                int r = idx >> 2, u = idx & 3;
                pa[i] = *(const uint4*)&Ap[(size_t)(m0 + r) * KP_TOT + (kt + 1) * 16 + u * 4];
                pb[i] = *(const uint4*)&Bp[(size_t)(n0 + r) * KP_TOT + (kt + 1) * 16 + u * 4];
            }
        }

#pragma unroll
        for (int ks = 0; ks < 2; ks++) {
            const int ko = ks * 8;
            uint32_t af[4][4], bf2[4][2];
#pragma unroll
            for (int mm = 0; mm < 4; mm++) {
                int rb = wm * 64 + mm * 16 + g;
                af[mm][0] = As[rb][ko + t];
                af[mm][1] = As[rb + 8][ko + t];
                af[mm][2] = As[rb][ko + t + 4];
                af[mm][3] = As[rb + 8][ko + t + 4];
            }
#pragma unroll
            for (int nn = 0; nn < 4; nn++) {
                int cb = wn * 32 + nn * 8 + g;
                bf2[nn][0] = Bs[cb][ko + t];
                bf2[nn][1] = Bs[cb][ko + t + 4];
            }
#pragma unroll
            for (int mm = 0; mm < 4; mm++)
#pragma unroll
                for (int nn = 0; nn < 4; nn++)
                    mma_fp16(acc[mm][nn], af[mm][0], af[mm][1], af[mm][2], af[mm][3],
                             bf2[nn][0], bf2[nn][1]);
        }
        __syncthreads();
    }

#pragma unroll
    for (int mm = 0; mm < 4; mm++)
#pragma unroll
        for (int nn = 0; nn < 4; nn++) {
            int row = m0 + wm * 64 + mm * 16 + g;
            int col = n0 + wn * 32 + nn * 8 + t * 2;
            *(float2*)&C[(size_t)row * ldc + col] =
                make_float2(acc[mm][nn][0], acc[mm][nn][1]);
            *(float2*)&C[(size_t)(row + 8) * ldc + col] =
                make_float2(acc[mm][nn][2], acc[mm][nn][3]);
        }
}

__global__ void __launch_bounds__(256) qkv_fp16()
{
    int ncol0 = blockIdx.x * 128;
    int m0    = blockIdx.y * 128;
    const uint32_t* Bp;
    float* Cp;
    int ldc, n0;
    if (ncol0 < 2048)      { Bp = g_WqT; Cp = g_q; ldc = QW; n0 = ncol0;        }
    else if (ncol0 < 2560) { Bp = g_WkT; Cp = g_k; ldc = KW; n0 = ncol0 - 2048; }
    else                   { Bp = g_WvT; Cp = g_v; ldc = KW; n0 = ncol0 - 2560; }
    gemm_fp16_tile(g_xP, Bp, Cp, ldc, m0, n0);
}

__global__ void __launch_bounds__(256) out_fp16(float* __restrict__ out)
{
    gemm_fp16_tile((const uint32_t*)g_oP, g_WoT, out, DMODEL,
                   blockIdx.y * 128, blockIdx.x * 128);
}

// ---------------------------------------------------------------------------
// RoPE (validated negated angle)
// ---------------------------------------------------------------------------
__global__ void __launch_bounds__(256) rope_kernel(int which)
{
    float* p     = which ? g_k : g_q;
    const int nh = which ? NKV : NH;
    int idx  = blockIdx.x * 256 + threadIdx.x;
    int dd   = idx & 63;
    int rest = idx >> 6;
    int head = rest & (nh - 1);
    int row  = rest / nh;
    if (row >= SB) return;
    int s = row >> 1;

    float e    = (float)(2 * dd) / 128.0f;
    float invf = 1.0f / powf(10000.0f, e);
    float ang  = -(float)s * invf;
    float c, sn;
    sincosf(ang, &c, &sn);

    float* base = p + (size_t)row * (nh * HD) + head * HD;
    float u1 = base[dd];
    float u2 = base[dd + 64];
    base[dd]      = u1 * c - u2 * sn;
    base[dd + 64] = u2 * c + u1 * sn;
}

// ---------------------------------------------------------------------------
// Flash attention v5: split-bf16 QK (validated) + fp16 PV with
// conflict-free pair-wise V commit (lane = jpair, warp-uniform d-block).
// ---------------------------------------------------------------------------
#define BSTR 68      // Q/K bf16-pair row stride (words)
#define VST  36      // V fp16-pair row stride (words), [d][jpair]
#define PST  36      // P fp16-pair row stride (words), [row][jpair]

__global__ void __launch_bounds__(256, 1) flash_tc()
{
    extern __shared__ uint32_t smu[];
    uint32_t* sQh = smu;                      // [128][BSTR]
    uint32_t* sQl = sQh + 128 * BSTR;         // [128][BSTR]
    uint32_t* sKh = sQl + 128 * BSTR;         // [64][BSTR]
    uint32_t* sKl = sKh + 64 * BSTR;          // [64][BSTR]
    uint32_t* sVp = sKl + 64 * BSTR;          // [128 d][VST] fp16x2 pairs along j
    uint32_t* sP  = sVp + 128 * VST;          // [8][16][PST] fp16x2 pairs along j

    const int qt  = 15 - blockIdx.x;
    const int bh  = blockIdx.y;
    const int b   = bh >> 4;
    const int h   = bh & 15;
    const int kvh = h >> 2;
    const int tid  = threadIdx.x;
    const int lane = tid & 31;
    const int w    = tid >> 5;
    const int g    = lane >> 2;
    const int t    = lane & 3;

    // Load + split + pack Q tile (128 x 128)
    for (int idx = tid; idx < 128 * 32; idx += 256) {
        int r  = idx >> 5;
        int c4 = (idx & 31) << 2;
        float4 q = *(const float4*)&g_q[((size_t)(qt * 128 + r) * BATCH + b) * QW + h * HD + c4];
        __nv_bfloat16 xh, xl, yh, yl, zh, zl, wh, wl;
        splitb(q.x, xh, xl); splitb(q.y, yh, yl);
        splitb(q.z, zh, zl); splitb(q.w, wh, wl);
        int p0 = r * BSTR + (c4 >> 1);
        sQh[p0]     = packb(xh, yh);
        sQh[p0 + 1] = packb(zh, wh);
        sQl[p0]     = packb(xl, yl);
        sQl[p0 + 1] = packb(zl, wl);
    }

    float oacc[16][4];
#pragma unroll
    for (int dt = 0; dt < 16; dt++)
#pragma unroll
        for (int i = 0; i < 4; i++) oacc[dt][i] = 0.0f;
    float m0 = -1e30f, m1 = -1e30f, l0 = 0.0f, l1 = 0.0f;

    const float sc = 0.08838834764831845f;
    const int r0 = qt * 128 + w * 16 + g;
    const int r1 = r0 + 8;
    uint32_t* pw = sP + w * 16 * PST;

    const int nkt = 2 * qt + 2;

    // Prefetch tile 0.
    // K: warp-uniform row j = w + 8i, lanes cover columns (coalesced).
    // V: lane = jpair (rows 2*lane, 2*lane+1), warp-uniform d-block (scattered, L2-hit).
    float4 pk[8], pva[4], pvb[4];
#pragma unroll
    for (int i = 0; i < 8; i++) {
        int idx = tid + i * 256;
        int j  = idx >> 5;
        int c4 = (idx & 31) << 2;
        pk[i] = *(const float4*)&g_k[((size_t)j * BATCH + b) * KW + kvh * HD + c4];
    }
#pragma unroll
    for (int it = 0; it < 4; it++) {
        int d0 = w * 16 + it * 4;
        size_t ga = ((size_t)(2 * lane) * BATCH + b) * KW + kvh * HD + d0;
        pva[it] = *(const float4*)&g_v[ga];
        pvb[it] = *(const float4*)&g_v[ga + (size_t)BATCH * KW];
    }

    for (int kt = 0; kt < nkt; kt++) {
        __syncthreads();
        // commit K (split bf16, coalesced) and V (fp16 [d][jpair], conflict-free)
#pragma unroll
        for (int i = 0; i < 8; i++) {
            int idx = tid + i * 256;
            int j  = idx >> 5;
            int c4 = (idx & 31) << 2;
            __nv_bfloat16 xh, xl, yh, yl, zh, zl, wh, wl;
            splitb(pk[i].x, xh, xl); splitb(pk[i].y, yh, yl);
            splitb(pk[i].z, zh, zl); splitb(pk[i].w, wh, wl);
            int p0 = j * BSTR + (c4 >> 1);
            sKh[p0]     = packb(xh, yh);
            sKh[p0 + 1] = packb(zh, wh);
            sKl[p0]     = packb(xl, yl);
            sKl[p0 + 1] = packb(zl, wl);
        }
#pragma unroll
        for (int it = 0; it < 4; it++) {
            int d0 = w * 16 + it * 4;
            sVp[(d0 + 0) * VST + lane] = packh(pva[it].x, pvb[it].x);
            sVp[(d0 + 1) * VST + lane] = packh(pva[it].y, pvb[it].y);
            sVp[(d0 + 2) * VST + lane] = packh(pva[it].z, pvb[it].z);
            sVp[(d0 + 3) * VST + lane] = packh(pva[it].w, pvb[it].w);
        }
        __syncthreads();

        // prefetch next tile while computing
        if (kt + 1 < nkt) {
#pragma unroll
            for (int i = 0; i < 8; i++) {
                int idx = tid + i * 256;
                int j  = idx >> 5;
                int c4 = (idx & 31) << 2;
                pk[i] = *(const float4*)&g_k[((size_t)((kt + 1) * 64 + j) * BATCH + b) * KW + kvh * HD + c4];
            }
#pragma unroll
            for (int it = 0; it < 4; it++) {
                int d0 = w * 16 + it * 4;
                size_t ga = ((size_t)((kt + 1) * 64 + 2 * lane) * BATCH + b) * KW + kvh * HD + d0;
                pva[it] = *(const float4*)&g_v[ga];
                pvb[it] = *(const float4*)&g_v[ga + (size_t)BATCH * KW];
            }
        }

        if (kt * 64 <= qt * 128 + w * 16 + 15) {
            // ---- scores: split-bf16 3-term ----
            float sacc[8][4];
#pragma unroll
            for (int nt = 0; nt < 8; nt++)
#pragma unroll
                for (int i = 0; i < 4; i++) sacc[nt][i] = 0.0f;

#pragma unroll
            for (int ks = 0; ks < 8; ks++) {
                const int qb = (w * 16) * BSTR + ks * 8;
                uint32_t ah0 = sQh[qb + g * BSTR + t];
                uint32_t ah1 = sQh[qb + (g + 8) * BSTR + t];
                uint32_t ah2 = sQh[qb + g * BSTR + t + 4];
                uint32_t ah3 = sQh[qb + (g + 8) * BSTR + t + 4];
                uint32_t al0 = sQl[qb + g * BSTR + t];
                uint32_t al1 = sQl[qb + (g + 8) * BSTR + t];
                uint32_t al2 = sQl[qb + g * BSTR + t + 4];
                uint32_t al3 = sQl[qb + (g + 8) * BSTR + t + 4];
#pragma unroll
                for (int nt = 0; nt < 8; nt++) {
                    const int kb = (nt * 8 + g) * BSTR + ks * 8;
                    uint32_t bh0 = sKh[kb + t], bh1 = sKh[kb + t + 4];
                    uint32_t bl0 = sKl[kb + t], bl1 = sKl[kb + t + 4];
                    mma_bf16(sacc[nt], ah0, ah1, ah2, ah3, bh0, bh1);
                    mma_bf16(sacc[nt], ah0, ah1, ah2, ah3, bl0, bl1);
                    mma_bf16(sacc[nt], al0, al1, al2, al3, bh0, bh1);
                }
            }

            // ---- scale + mask + online softmax ----
            const bool need_mask = (kt >= 2 * qt);
            float mx0 = -1e30f, mx1 = -1e30f;
#pragma unroll
            for (int nt = 0; nt < 8; nt++) {
                int c0 = kt * 64 + nt * 8 + 2 * t;
#pragma unroll
                for (int i = 0; i < 4; i++) {
                    float v = sacc[nt][i] * sc;
                    if (need_mask) {
                        int col = c0 + (i & 1);
                        int row = (i < 2) ? r0 : r1;
                        if (col > row) v = -1e30f;
                    }
                    sacc[nt][i] = v;
                }
                mx0 = fmaxf(mx0, fmaxf(sacc[nt][0], sacc[nt][1]));
                mx1 = fmaxf(mx1, fmaxf(sacc[nt][2], sacc[nt][3]));
            }
#pragma unroll
            for (int off = 1; off <= 2; off <<= 1) {
                mx0 = fmaxf(mx0, __shfl_xor_sync(0xffffffffu, mx0, off));
                mx1 = fmaxf(mx1, __shfl_xor_sync(0xffffffffu, mx1, off));
            }
            float mn0 = fmaxf(m0, mx0), mn1 = fmaxf(m1, mx1);
            float corr0 = expf(m0 - mn0), corr1 = expf(m1 - mn1);
            m0 = mn0; m1 = mn1;

            float sum0 = 0.0f, sum1 = 0.0f;
#pragma unroll
            for (int nt = 0; nt < 8; nt++) {
                float p00 = expf(sacc[nt][0] - m0);
                float p01 = expf(sacc[nt][1] - m0);
                float p10 = expf(sacc[nt][2] - m1);
                float p11 = expf(sacc[nt][3] - m1);
                sum0 += p00 + p01;
                sum1 += p10 + p11;
                pw[g * PST + nt * 4 + t]       = packh(p00, p01);
                pw[(g + 8) * PST + nt * 4 + t] = packh(p10, p11);
            }
#pragma unroll
            for (int off = 1; off <= 2; off <<= 1) {
                sum0 += __shfl_xor_sync(0xffffffffu, sum0, off);
                sum1 += __shfl_xor_sync(0xffffffffu, sum1, off);
            }
            l0 = l0 * corr0 + sum0;
            l1 = l1 * corr1 + sum1;
#pragma unroll
            for (int dt = 0; dt < 16; dt++) {
                oacc[dt][0] *= corr0; oacc[dt][1] *= corr0;
                oacc[dt][2] *= corr1; oacc[dt][3] *= corr1;
            }
            __syncwarp();

            // ---- O += P @ V, single fp16 k16 ----
#pragma unroll
            for (int ks = 0; ks < 4; ks++) {
                uint32_t a0 = pw[g * PST + ks * 8 + t];
                uint32_t a1 = pw[(g + 8) * PST + ks * 8 + t];
                uint32_t a2 = pw[g * PST + ks * 8 + t + 4];
                uint32_t a3 = pw[(g + 8) * PST + ks * 8 + t + 4];
#pragma unroll
                for (int dt = 0; dt < 16; dt++) {
                    uint32_t b0 = sVp[(dt * 8 + g) * VST + ks * 8 + t];
                    uint32_t b1 = sVp[(dt * 8 + g) * VST + ks * 8 + t + 4];
                    mma_fp16(oacc[dt], a0, a1, a2, a3, b0, b1);
                }
            }
        }
    }

    // ---- epilogue: write fp16-packed O directly (feeds out_fp16 GEMM) ----
    float invl0 = 1.0f / l0, invl1 = 1.0f / l1;
    const size_t row0 = (size_t)r0 * BATCH + b;
    const size_t row1 = (size_t)r1 * BATCH + b;
#pragma unroll
    for (int dt = 0; dt < 16; dt++) {
        int kp = h * 64 + dt * 4 + t;     // (h*HD + dt*8 + 2t) / 2
        g_oP[row0 * KP_TOT + kp] = packh(oacc[dt][0] * invl0, oacc[dt][1] * invl0);
        g_oP[row1 * KP_TOT + kp] = packh(oacc[dt][2] * invl1, oacc[dt][3] * invl1);
    }
}

// ---------------------------------------------------------------------------
// Launch
// ---------------------------------------------------------------------------
extern "C" void kernel_launch(void* const* d_in, const int* in_sizes, int n_in,
                              void* d_out, int out_size)
{
    int ix = -1, ik = -1, iv = -1, ia = -1, ib = -1;
    for (int i = 0; i < n_in; i++) {
        if (in_sizes[i] == 8388608) { ix = i; }
        else if (in_sizes[i] == 1048576) { if (ik < 0) ik = i; else iv = i; }
        else if (in_sizes[i] == 4194304) { if (ia < 0) ia = i; else ib = i; }
    }
    int iq, io;
    if (ix == 0) { iq = ia; io = ib; }
    else         { io = ia; iq = ib; }

    const float* x  = (const float*)d_in[ix];
    const float* Wq = (const float*)d_in[iq];
    const float* Wk = (const float*)d_in[ik];
    const float* Wv = (const float*)d_in[iv];
    const float* Wo = (const float*)d_in[io];
    float* out = (float*)d_out;

    uint32_t* xP;  cudaGetSymbolAddress((void**)&xP,  g_xP);
    uint32_t* WqT; cudaGetSymbolAddress((void**)&WqT, g_WqT);
    uint32_t* WkT; cudaGetSymbolAddress((void**)&WkT, g_WkT);
    uint32_t* WvT; cudaGetSymbolAddress((void**)&WvT, g_WvT);
    uint32_t* WoT; cudaGetSymbolAddress((void**)&WoT, g_WoT);

    const int N4 = SB * DMODEL / 4;
    pack_h2<<<(N4 + 255) / 256, 256>>>(x, xP, N4);
    transpose_pack<<<dim3(32, 32), 256>>>(Wq, WqT, 2048);
    transpose_pack<<<dim3( 8, 32), 256>>>(Wk, WkT,  512);
    transpose_pack<<<dim3( 8, 32), 256>>>(Wv, WvT,  512);
    transpose_pack<<<dim3(32, 32), 256>>>(Wo, WoT, 2048);

    qkv_fp16<<<dim3(24, 32), 256>>>();

    rope_kernel<<<(SB * NH  * 64) / 256, 256>>>(0);
    rope_kernel<<<(SB * NKV * 64) / 256, 256>>>(1);

    const int FLASH_SMEM =
        (2 * 128 * BSTR + 2 * 64 * BSTR + 128 * VST + 8 * 16 * PST) * (int)sizeof(uint32_t);
    cudaFuncSetAttribute(flash_tc, cudaFuncAttributeMaxDynamicSharedMemorySize, FLASH_SMEM);
    flash_tc<<<dim3(16, 32), 256, FLASH_SMEM>>>();

    out_fp16<<<dim3(16, 32), 256>>>(out);
}

// round 16
// speedup vs baseline: 1.0528x; 1.0528x over previous
#include <cuda_runtime.h>
#include <cuda_bf16.h>
#include <cuda_fp16.h>
#include <math.h>
#include <stdint.h>

// Problem constants
#define S_LEN 2048
#define BATCH 2
#define DMODEL 2048
#define NH 16
#define NKV 4
#define HD 128
#define SB (S_LEN*BATCH)
#define QW (NH*HD)
#define KW (NKV*HD)
#define KP_TOT 1024              // 2048 k / 2 per pair

// Scratch
__device__ float g_q[SB*QW];
__device__ float g_k[SB*KW];
__device__ float g_v[SB*KW];
// fp16-packed operands
__device__ uint32_t g_xP [SB*KP_TOT];
__device__ uint32_t g_oP [SB*KP_TOT];
__device__ uint32_t g_WqT[2048*KP_TOT];
__device__ uint32_t g_WkT[ 512*KP_TOT];
__device__ uint32_t g_WvT[ 512*KP_TOT];
__device__ uint32_t g_WoT[2048*KP_TOT];

// ---------------------------------------------------------------------------
// helpers
// ---------------------------------------------------------------------------
__device__ __forceinline__ void splitb(float x, __nv_bfloat16& h, __nv_bfloat16& l) {
    h = __float2bfloat16(x);
    l = __float2bfloat16(x - __bfloat162float(h));
}
__device__ __forceinline__ uint32_t packb(__nv_bfloat16 lo_k, __nv_bfloat16 hi_k) {
    __nv_bfloat162 p = __halves2bfloat162(lo_k, hi_k);
    return *(uint32_t*)&p;
}
__device__ __forceinline__ uint32_t packh(float a, float b) {
    __half2 h = __floats2half2_rn(a, b);   // .x = a (low bits) = even k
    return *(uint32_t*)&h;
}

__device__ __forceinline__ void mma_bf16(float* c,
    uint32_t a0, uint32_t a1, uint32_t a2, uint32_t a3,
    uint32_t b0, uint32_t b1)
{
    asm volatile(
        "mma.sync.aligned.m16n8k16.row.col.f32.bf16.bf16.f32 "
        "{%0,%1,%2,%3}, {%4,%5,%6,%7}, {%8,%9}, {%0,%1,%2,%3};"
        : "+f"(c[0]), "+f"(c[1]), "+f"(c[2]), "+f"(c[3])
        : "r"(a0), "r"(a1), "r"(a2), "r"(a3), "r"(b0), "r"(b1));
}
__device__ __forceinline__ void mma_fp16(float* c,
    uint32_t a0, uint32_t a1, uint32_t a2, uint32_t a3,
    uint32_t b0, uint32_t b1)
{
    asm volatile(
        "mma.sync.aligned.m16n8k16.row.col.f32.f16.f16.f32 "
        "{%0,%1,%2,%3}, {%4,%5,%6,%7}, {%8,%9}, {%0,%1,%2,%3};"
        : "+f"(c[0]), "+f"(c[1]), "+f"(c[2]), "+f"(c[3])
        : "r"(a0), "r"(a1), "r"(a2), "r"(a3), "r"(b0), "r"(b1));
}
__device__ __forceinline__ void ldsm4(uint32_t& r0, uint32_t& r1,
                                      uint32_t& r2, uint32_t& r3, uint32_t addr)
{
    asm volatile("ldmatrix.sync.aligned.m8n8.x4.shared.b16 {%0,%1,%2,%3}, [%4];"
                 : "=r"(r0), "=r"(r1), "=r"(r2), "=r"(r3) : "r"(addr));
}

// ---------------------------------------------------------------------------
// prep kernels
// ---------------------------------------------------------------------------
__global__ void __launch_bounds__(256) pack_h2(
    const float* __restrict__ src, uint32_t* __restrict__ dst, int n4)
{
    int i = blockIdx.x * 256 + threadIdx.x;
    if (i >= n4) return;
    float4 v = ((const float4*)src)[i];
    ((uint2*)dst)[i] = make_uint2(packh(v.x, v.y), packh(v.z, v.w));
}

__global__ void __launch_bounds__(256) transpose_pack(
    const float* __restrict__ W, uint32_t* __restrict__ WT, int N)
{
    __shared__ float sm[64][68];
    const int n0 = blockIdx.x * 64;
    const int k0 = blockIdx.y * 64;
    const int tid = threadIdx.x;
#pragma unroll
    for (int i = 0; i < 4; i++) {
        int idx = tid + i * 256;
        int kr = idx >> 4;
        int nq = idx & 15;
        float4 v = *(const float4*)&W[(size_t)(k0 + kr) * N + n0 + nq * 4];
        sm[kr][nq * 4 + 0] = v.x;
        sm[kr][nq * 4 + 1] = v.y;
        sm[kr][nq * 4 + 2] = v.z;
        sm[kr][nq * 4 + 3] = v.w;
    }
    __syncthreads();
    const int kp = tid & 31;
    const int nb = tid >> 5;
#pragma unroll
    for (int ph = 0; ph < 8; ph++) {
        int n = nb + ph * 8;
        WT[(size_t)(n0 + n) * KP_TOT + (k0 >> 1) + kp] =
            packh(sm[2 * kp][n], sm[2 * kp + 1][n]);
    }
}

// ---------------------------------------------------------------------------
// fp16 tensor-core GEMM tile — fragment loads via ldmatrix (this round's change)
// ---------------------------------------------------------------------------
#define FSTR 36

__device__ __forceinline__ void gemm_fp16_tile(
    const uint32_t* __restrict__ Ap, const uint32_t* __restrict__ Bp,
    float* __restrict__ C, int ldc, int m0, int n0)
{
    __shared__ uint32_t As[128][FSTR];
    __shared__ uint32_t Bs[128][FSTR];

    const int tid  = threadIdx.x;
    const int lane = tid & 31;
    const int wid  = tid >> 5;
    const int wm   = wid >> 2;
    const int wn   = wid & 3;
    const int g    = lane >> 2;
    const int t    = lane & 3;

    // ldmatrix per-lane source row/col (kpair units)
    const int aRow = (lane & 7) + ((lane >> 3) & 1) * 8;   // tile row
    const int aCol = (lane >> 4) * 4;                      // 0 or 4
    const int bRow = (lane & 7) + ((lane >> 4) & 1) * 8;
    const int bCol = ((lane >> 3) & 1) * 4;

    const uint32_t sAu = (uint32_t)__cvta_generic_to_shared(&As[0][0]);
    const uint32_t sBu = (uint32_t)__cvta_generic_to_shared(&Bs[0][0]);

    float acc[4][4][4];
#pragma unroll
    for (int mm = 0; mm < 4; mm++)
#pragma unroll
        for (int nn = 0; nn < 4; nn++)
#pragma unroll
            for (int i = 0; i < 4; i++) acc[mm][nn][i] = 0.0f;

    uint4 pa[2], pb[2];
#pragma unroll
    for (int i = 0; i < 2; i++) {
        int idx = tid + i * 256;
        int r = idx >> 2, u = idx & 3;
        pa[i] = *(const uint4*)&Ap[(size_t)(m0 + r) * KP_TOT + u * 4];
        pb[i] = *(const uint4*)&Bp[(size_t)(n0 + r) * KP_TOT + u * 4];
    }

    for (int kt = 0; kt < 64; kt++) {
#pragma unroll
        for (int i = 0; i < 2; i++) {
            int idx = tid + i * 256;
            int r = idx >> 2, u = idx & 3;
            *(uint4*)&As[r][u * 4] = pa[i];
            *(uint4*)&Bs[r][u * 4] = pb[i];
        }
        __syncthreads();

        if (kt + 1 < 64) {
#pragma unroll
            for (int i = 0; i < 2; i++) {
                int idx = tid + i * 256;
                int r = idx >> 2, u = idx & 3;
                pa[i] = *(const uint4*)&Ap[(size_t)(m0 + r) * KP_TOT + (kt + 1) * 16 + u * 4];
                pb[i] = *(const uint4*)&Bp[(size_t)(n0 + r) * KP_TOT + (kt + 1) * 16 + u * 4];
            }
        }

#pragma unroll
        for (int ks = 0; ks < 2; ks++) {
            const int ko = ks * 8;
            uint32_t af[4][4], bf2[4][2];
#pragma unroll
            for (int mm = 0; mm < 4; mm++) {
                uint32_t addr = sAu +
                    (((wm * 64 + mm * 16 + aRow) * FSTR) + ko + aCol) * 4;
                ldsm4(af[mm][0], af[mm][1], af[mm][2], af[mm][3], addr);
            }
#pragma unroll
            for (int nn = 0; nn < 4; nn += 2) {
                uint32_t addr = sBu +
                    (((wn * 32 + nn * 8 + bRow) * FSTR) + ko + bCol) * 4;
                ldsm4(bf2[nn][0], bf2[nn][1], bf2[nn + 1][0], bf2[nn + 1][1], addr);
            }
#pragma unroll
            for (int mm = 0; mm < 4; mm++)
#pragma unroll
                for (int nn = 0; nn < 4; nn++)
                    mma_fp16(acc[mm][nn], af[mm][0], af[mm][1], af[mm][2], af[mm][3],
                             bf2[nn][0], bf2[nn][1]);
        }
        __syncthreads();
    }

#pragma unroll
    for (int mm = 0; mm < 4; mm++)
#pragma unroll
        for (int nn = 0; nn < 4; nn++) {
            int row = m0 + wm * 64 + mm * 16 + g;
            int col = n0 + wn * 32 + nn * 8 + t * 2;
            *(float2*)&C[(size_t)row * ldc + col] =
                make_float2(acc[mm][nn][0], acc[mm][nn][1]);
            *(float2*)&C[(size_t)(row + 8) * ldc + col] =
                make_float2(acc[mm][nn][2], acc[mm][nn][3]);
        }
}

__global__ void __launch_bounds__(256) qkv_fp16()
{
    int ncol0 = blockIdx.x * 128;
    int m0    = blockIdx.y * 128;
    const uint32_t* Bp;
    float* Cp;
    int ldc, n0;
    if (ncol0 < 2048)      { Bp = g_WqT; Cp = g_q; ldc = QW; n0 = ncol0;        }
    else if (ncol0 < 2560) { Bp = g_WkT; Cp = g_k; ldc = KW; n0 = ncol0 - 2048; }
    else                   { Bp = g_WvT; Cp = g_v; ldc = KW; n0 = ncol0 - 2560; }
    gemm_fp16_tile(g_xP, Bp, Cp, ldc, m0, n0);
}

__global__ void __launch_bounds__(256) out_fp16(float* __restrict__ out)
{
    gemm_fp16_tile((const uint32_t*)g_oP, g_WoT, out, DMODEL,
                   blockIdx.y * 128, blockIdx.x * 128);
}

// ---------------------------------------------------------------------------
// RoPE (validated negated angle)
// ---------------------------------------------------------------------------
__global__ void __launch_bounds__(256) rope_kernel(int which)
{
    float* p     = which ? g_k : g_q;
    const int nh = which ? NKV : NH;
    int idx  = blockIdx.x * 256 + threadIdx.x;
    int dd   = idx & 63;
    int rest = idx >> 6;
    int head = rest & (nh - 1);
    int row  = rest / nh;
    if (row >= SB) return;
    int s = row >> 1;

    float e    = (float)(2 * dd) / 128.0f;
    float invf = 1.0f / powf(10000.0f, e);
    float ang  = -(float)s * invf;
    float c, sn;
    sincosf(ang, &c, &sn);

    float* base = p + (size_t)row * (nh * HD) + head * HD;
    float u1 = base[dd];
    float u2 = base[dd + 64];
    base[dd]      = u1 * c - u2 * sn;
    base[dd + 64] = u2 * c + u1 * sn;
}

// ---------------------------------------------------------------------------
// Flash attention v5 (round-15, unchanged this round)
// ---------------------------------------------------------------------------
#define BSTR 68      // Q/K bf16-pair row stride (words)
#define VST  36      // V fp16-pair row stride (words), [d][jpair]
#define PST  36      // P fp16-pair row stride (words), [row][jpair]

__global__ void __launch_bounds__(256, 1) flash_tc()
{
    extern __shared__ uint32_t smu[];
    uint32_t* sQh = smu;                      // [128][BSTR]
    uint32_t* sQl = sQh + 128 * BSTR;         // [128][BSTR]
    uint32_t* sKh = sQl + 128 * BSTR;         // [64][BSTR]
    uint32_t* sKl = sKh + 64 * BSTR;          // [64][BSTR]
    uint32_t* sVp = sKl + 64 * BSTR;          // [128 d][VST] fp16x2 pairs along j
    uint32_t* sP  = sVp + 128 * VST;          // [8][16][PST] fp16x2 pairs along j

    const int qt  = 15 - blockIdx.x;
    const int bh  = blockIdx.y;
    const int b   = bh >> 4;
    const int h   = bh & 15;
    const int kvh = h >> 2;
    const int tid  = threadIdx.x;
    const int lane = tid & 31;
    const int w    = tid >> 5;
    const int g    = lane >> 2;
    const int t    = lane & 3;

    // Load + split + pack Q tile (128 x 128)
    for (int idx = tid; idx < 128 * 32; idx += 256) {
        int r  = idx >> 5;
        int c4 = (idx & 31) << 2;
        float4 q = *(const float4*)&g_q[((size_t)(qt * 128 + r) * BATCH + b) * QW + h * HD + c4];
        __nv_bfloat16 xh, xl, yh, yl, zh, zl, wh, wl;
        splitb(q.x, xh, xl); splitb(q.y, yh, yl);
        splitb(q.z, zh, zl); splitb(q.w, wh, wl);
        int p0 = r * BSTR + (c4 >> 1);
        sQh[p0]     = packb(xh, yh);
        sQh[p0 + 1] = packb(zh, wh);
        sQl[p0]     = packb(xl, yl);
        sQl[p0 + 1] = packb(zl, wl);
    }

    float oacc[16][4];
#pragma unroll
    for (int dt = 0; dt < 16; dt++)
#pragma unroll
        for (int i = 0; i < 4; i++) oacc[dt][i] = 0.0f;
    float m0 = -1e30f, m1 = -1e30f, l0 = 0.0f, l1 = 0.0f;

    const float sc = 0.08838834764831845f;
    const int r0 = qt * 128 + w * 16 + g;
    const int r1 = r0 + 8;
    uint32_t* pw = sP + w * 16 * PST;

    const int nkt = 2 * qt + 2;

    float4 pk[8], pva[4], pvb[4];
#pragma unroll
    for (int i = 0; i < 8; i++) {
        int idx = tid + i * 256;
        int j  = idx >> 5;
        int c4 = (idx & 31) << 2;
        pk[i] = *(const float4*)&g_k[((size_t)j * BATCH + b) * KW + kvh * HD + c4];
    }
#pragma unroll
    for (int it = 0; it < 4; it++) {
        int d0 = w * 16 + it * 4;
        size_t ga = ((size_t)(2 * lane) * BATCH + b) * KW + kvh * HD + d0;
        pva[it] = *(const float4*)&g_v[ga];
        pvb[it] = *(const float4*)&g_v[ga + (size_t)BATCH * KW];
    }

    for (int kt = 0; kt < nkt; kt++) {
        __syncthreads();
#pragma unroll
        for (int i = 0; i < 8; i++) {
            int idx = tid + i * 256;
            int j  = idx >> 5;
            int c4 = (idx & 31) << 2;
            __nv_bfloat16 xh, xl, yh, yl, zh, zl, wh, wl;
            splitb(pk[i].x, xh, xl); splitb(pk[i].y, yh, yl);
            splitb(pk[i].z, zh, zl); splitb(pk[i].w, wh, wl);
            int p0 = j * BSTR + (c4 >> 1);
            sKh[p0]     = packb(xh, yh);
            sKh[p0 + 1] = packb(zh, wh);
            sKl[p0]     = packb(xl, yl);
            sKl[p0 + 1] = packb(zl, wl);
        }
#pragma unroll
        for (int it = 0; it < 4; it++) {
            int d0 = w * 16 + it * 4;
            sVp[(d0 + 0) * VST + lane] = packh(pva[it].x, pvb[it].x);
            sVp[(d0 + 1) * VST + lane] = packh(pva[it].y, pvb[it].y);
            sVp[(d0 + 2) * VST + lane] = packh(pva[it].z, pvb[it].z);
            sVp[(d0 + 3) * VST + lane] = packh(pva[it].w, pvb[it].w);
        }
        __syncthreads();

        if (kt + 1 < nkt) {
#pragma unroll
            for (int i = 0; i < 8; i++) {
                int idx = tid + i * 256;
                int j  = idx >> 5;
                int c4 = (idx & 31) << 2;
                pk[i] = *(const float4*)&g_k[((size_t)((kt + 1) * 64 + j) * BATCH + b) * KW + kvh * HD + c4];
            }
#pragma unroll
            for (int it = 0; it < 4; it++) {
                int d0 = w * 16 + it * 4;
                size_t ga = ((size_t)((kt + 1) * 64 + 2 * lane) * BATCH + b) * KW + kvh * HD + d0;
                pva[it] = *(const float4*)&g_v[ga];
                pvb[it] = *(const float4*)&g_v[ga + (size_t)BATCH * KW];
            }
        }

        if (kt * 64 <= qt * 128 + w * 16 + 15) {
            float sacc[8][4];
#pragma unroll
            for (int nt = 0; nt < 8; nt++)
#pragma unroll
                for (int i = 0; i < 4; i++) sacc[nt][i] = 0.0f;

#pragma unroll
            for (int ks = 0; ks < 8; ks++) {
                const int qb = (w * 16) * BSTR + ks * 8;
                uint32_t ah0 = sQh[qb + g * BSTR + t];
                uint32_t ah1 = sQh[qb + (g + 8) * BSTR + t];
                uint32_t ah2 = sQh[qb + g * BSTR + t + 4];
                uint32_t ah3 = sQh[qb + (g + 8) * BSTR + t + 4];
                uint32_t al0 = sQl[qb + g * BSTR + t];
                uint32_t al1 = sQl[qb + (g + 8) * BSTR + t];
                uint32_t al2 = sQl[qb + g * BSTR + t + 4];
                uint32_t al3 = sQl[qb + (g + 8) * BSTR + t + 4];
#pragma unroll
                for (int nt = 0; nt < 8; nt++) {
                    const int kb = (nt * 8 + g) * BSTR + ks * 8;
                    uint32_t bh0 = sKh[kb + t], bh1 = sKh[kb + t + 4];
                    uint32_t bl0 = sKl[kb + t], bl1 = sKl[kb + t + 4];
                    mma_bf16(sacc[nt], ah0, ah1, ah2, ah3, bh0, bh1);
                    mma_bf16(sacc[nt], ah0, ah1, ah2, ah3, bl0, bl1);
                    mma_bf16(sacc[nt], al0, al1, al2, al3, bh0, bh1);
                }
            }

            const bool need_mask = (kt >= 2 * qt);
            float mx0 = -1e30f, mx1 = -1e30f;
#pragma unroll
            for (int nt = 0; nt < 8; nt++) {
                int c0 = kt * 64 + nt * 8 + 2 * t;
#pragma unroll
                for (int i = 0; i < 4; i++) {
                    float v = sacc[nt][i] * sc;
                    if (need_mask) {
                        int col = c0 + (i & 1);
                        int row = (i < 2) ? r0 : r1;
                        if (col > row) v = -1e30f;
                    }
                    sacc[nt][i] = v;
                }
                mx0 = fmaxf(mx0, fmaxf(sacc[nt][0], sacc[nt][1]));
                mx1 = fmaxf(mx1, fmaxf(sacc[nt][2], sacc[nt][3]));
            }
#pragma unroll
            for (int off = 1; off <= 2; off <<= 1) {
                mx0 = fmaxf(mx0, __shfl_xor_sync(0xffffffffu, mx0, off));
                mx1 = fmaxf(mx1, __shfl_xor_sync(0xffffffffu, mx1, off));
            }
            float mn0 = fmaxf(m0, mx0), mn1 = fmaxf(m1, mx1);
            float corr0 = expf(m0 - mn0), corr1 = expf(m1 - mn1);
            m0 = mn0; m1 = mn1;

            float sum0 = 0.0f, sum1 = 0.0f;
#pragma unroll
            for (int nt = 0; nt < 8; nt++) {
                float p00 = expf(sacc[nt][0] - m0);
                float p01 = expf(sacc[nt][1] - m0);
                float p10 = expf(sacc[nt][2] - m1);
                float p11 = expf(sacc[nt][3] - m1);
                sum0 += p00 + p01;
                sum1 += p10 + p11;
                pw[g * PST + nt * 4 + t]       = packh(p00, p01);
                pw[(g + 8) * PST + nt * 4 + t] = packh(p10, p11);
            }
#pragma unroll
            for (int off = 1; off <= 2; off <<= 1) {
                sum0 += __shfl_xor_sync(0xffffffffu, sum0, off);
                sum1 += __shfl_xor_sync(0xffffffffu, sum1, off);
            }
            l0 = l0 * corr0 + sum0;
            l1 = l1 * corr1 + sum1;
#pragma unroll
            for (int dt = 0; dt < 16; dt++) {
                oacc[dt][0] *= corr0; oacc[dt][1] *= corr0;
                oacc[dt][2] *= corr1; oacc[dt][3] *= corr1;
            }
            __syncwarp();

#pragma unroll
            for (int ks = 0; ks < 4; ks++) {
                uint32_t a0 = pw[g * PST + ks * 8 + t];
                uint32_t a1 = pw[(g + 8) * PST + ks * 8 + t];
                uint32_t a2 = pw[g * PST + ks * 8 + t + 4];
                uint32_t a3 = pw[(g + 8) * PST + ks * 8 + t + 4];
#pragma unroll
                for (int dt = 0; dt < 16; dt++) {
                    uint32_t b0 = sVp[(dt * 8 + g) * VST + ks * 8 + t];
                    uint32_t b1 = sVp[(dt * 8 + g) * VST + ks * 8 + t + 4];
                    mma_fp16(oacc[dt], a0, a1, a2, a3, b0, b1);
                }
            }
        }
    }

    float invl0 = 1.0f / l0, invl1 = 1.0f / l1;
    const size_t row0 = (size_t)r0 * BATCH + b;
    const size_t row1 = (size_t)r1 * BATCH + b;
#pragma unroll
    for (int dt = 0; dt < 16; dt++) {
        int kp = h * 64 + dt * 4 + t;
        g_oP[row0 * KP_TOT + kp] = packh(oacc[dt][0] * invl0, oacc[dt][1] * invl0);
        g_oP[row1 * KP_TOT + kp] = packh(oacc[dt][2] * invl1, oacc[dt][3] * invl1);
    }
}

// ---------------------------------------------------------------------------
// Launch
// ---------------------------------------------------------------------------
extern "C" void kernel_launch(void* const* d_in, const int* in_sizes, int n_in,
                              void* d_out, int out_size)
{
    int ix = -1, ik = -1, iv = -1, ia = -1, ib = -1;
    for (int i = 0; i < n_in; i++) {
        if (in_sizes[i] == 8388608) { ix = i; }
        else if (in_sizes[i] == 1048576) { if (ik < 0) ik = i; else iv = i; }
        else if (in_sizes[i] == 4194304) { if (ia < 0) ia = i; else ib = i; }
    }
    int iq, io;
    if (ix == 0) { iq = ia; io = ib; }
    else         { io = ia; iq = ib; }

    const float* x  = (const float*)d_in[ix];
    const float* Wq = (const float*)d_in[iq];
    const float* Wk = (const float*)d_in[ik];
    const float* Wv = (const float*)d_in[iv];
    const float* Wo = (const float*)d_in[io];
    float* out = (float*)d_out;

    uint32_t* xP;  cudaGetSymbolAddress((void**)&xP,  g_xP);
    uint32_t* WqT; cudaGetSymbolAddress((void**)&WqT, g_WqT);
    uint32_t* WkT; cudaGetSymbolAddress((void**)&WkT, g_WkT);
    uint32_t* WvT; cudaGetSymbolAddress((void**)&WvT, g_WvT);
    uint32_t* WoT; cudaGetSymbolAddress((void**)&WoT, g_WoT);

    const int N4 = SB * DMODEL / 4;
    pack_h2<<<(N4 + 255) / 256, 256>>>(x, xP, N4);
    transpose_pack<<<dim3(32, 32), 256>>>(Wq, WqT, 2048);
    transpose_pack<<<dim3( 8, 32), 256>>>(Wk, WkT,  512);
    transpose_pack<<<dim3( 8, 32), 256>>>(Wv, WvT,  512);
    transpose_pack<<<dim3(32, 32), 256>>>(Wo, WoT, 2048);

    qkv_fp16<<<dim3(24, 32), 256>>>();

    rope_kernel<<<(SB * NH  * 64) / 256, 256>>>(0);
    rope_kernel<<<(SB * NKV * 64) / 256, 256>>>(1);

    const int FLASH_SMEM =
        (2 * 128 * BSTR + 2 * 64 * BSTR + 128 * VST + 8 * 16 * PST) * (int)sizeof(uint32_t);
    cudaFuncSetAttribute(flash_tc, cudaFuncAttributeMaxDynamicSharedMemorySize, FLASH_SMEM);
    flash_tc<<<dim3(16, 32), 256, FLASH_SMEM>>>();

    out_fp16<<<dim3(16, 32), 256>>>(out);
}

// round 17
// speedup vs baseline: 1.0648x; 1.0115x over previous
#include <cuda_runtime.h>
#include <cuda_bf16.h>
#include <cuda_fp16.h>
#include <math.h>
#include <stdint.h>

// Problem constants
#define S_LEN 2048
#define BATCH 2
#define DMODEL 2048
#define NH 16
#define NKV 4
#define HD 128
#define SB (S_LEN*BATCH)
#define QW (NH*HD)
#define KW (NKV*HD)
#define KP_TOT 1024              // 2048 k / 2 per pair

// Scratch
__device__ float g_q[SB*QW];
__device__ float g_k[SB*KW];
__device__ float g_v[SB*KW];
// fp16-packed operands
__device__ uint32_t g_xP [SB*KP_TOT];
__device__ uint32_t g_oP [SB*KP_TOT];
__device__ uint32_t g_WqT[2048*KP_TOT];
__device__ uint32_t g_WkT[ 512*KP_TOT];
__device__ uint32_t g_WvT[ 512*KP_TOT];
__device__ uint32_t g_WoT[2048*KP_TOT];

// ---------------------------------------------------------------------------
// helpers
// ---------------------------------------------------------------------------
__device__ __forceinline__ void splitb(float x, __nv_bfloat16& h, __nv_bfloat16& l) {
    h = __float2bfloat16(x);
    l = __float2bfloat16(x - __bfloat162float(h));
}
__device__ __forceinline__ uint32_t packb(__nv_bfloat16 lo_k, __nv_bfloat16 hi_k) {
    __nv_bfloat162 p = __halves2bfloat162(lo_k, hi_k);
    return *(uint32_t*)&p;
}
__device__ __forceinline__ uint32_t packh(float a, float b) {
    __half2 h = __floats2half2_rn(a, b);   // .x = a (low bits) = even k
    return *(uint32_t*)&h;
}

__device__ __forceinline__ void mma_bf16(float* c,
    uint32_t a0, uint32_t a1, uint32_t a2, uint32_t a3,
    uint32_t b0, uint32_t b1)
{
    asm volatile(
        "mma.sync.aligned.m16n8k16.row.col.f32.bf16.bf16.f32 "
        "{%0,%1,%2,%3}, {%4,%5,%6,%7}, {%8,%9}, {%0,%1,%2,%3};"
        : "+f"(c[0]), "+f"(c[1]), "+f"(c[2]), "+f"(c[3])
        : "r"(a0), "r"(a1), "r"(a2), "r"(a3), "r"(b0), "r"(b1));
}
__device__ __forceinline__ void mma_fp16(float* c,
    uint32_t a0, uint32_t a1, uint32_t a2, uint32_t a3,
    uint32_t b0, uint32_t b1)
{
    asm volatile(
        "mma.sync.aligned.m16n8k16.row.col.f32.f16.f16.f32 "
        "{%0,%1,%2,%3}, {%4,%5,%6,%7}, {%8,%9}, {%0,%1,%2,%3};"
        : "+f"(c[0]), "+f"(c[1]), "+f"(c[2]), "+f"(c[3])
        : "r"(a0), "r"(a1), "r"(a2), "r"(a3), "r"(b0), "r"(b1));
}
__device__ __forceinline__ void ldsm4(uint32_t& r0, uint32_t& r1,
                                      uint32_t& r2, uint32_t& r3, uint32_t addr)
{
    asm volatile("ldmatrix.sync.aligned.m8n8.x4.shared.b16 {%0,%1,%2,%3}, [%4];"
                 : "=r"(r0), "=r"(r1), "=r"(r2), "=r"(r3) : "r"(addr));
}

// ---------------------------------------------------------------------------
// prep kernels
// ---------------------------------------------------------------------------
__global__ void __launch_bounds__(256) pack_h2(
    const float* __restrict__ src, uint32_t* __restrict__ dst, int n4)
{
    int i = blockIdx.x * 256 + threadIdx.x;
    if (i >= n4) return;
    float4 v = ((const float4*)src)[i];
    ((uint2*)dst)[i] = make_uint2(packh(v.x, v.y), packh(v.z, v.w));
}

__global__ void __launch_bounds__(256) transpose_pack(
    const float* __restrict__ W, uint32_t* __restrict__ WT, int N)
{
    __shared__ float sm[64][68];
    const int n0 = blockIdx.x * 64;
    const int k0 = blockIdx.y * 64;
    const int tid = threadIdx.x;
#pragma unroll
    for (int i = 0; i < 4; i++) {
        int idx = tid + i * 256;
        int kr = idx >> 4;
        int nq = idx & 15;
        float4 v = *(const float4*)&W[(size_t)(k0 + kr) * N + n0 + nq * 4];
        sm[kr][nq * 4 + 0] = v.x;
        sm[kr][nq * 4 + 1] = v.y;
        sm[kr][nq * 4 + 2] = v.z;
        sm[kr][nq * 4 + 3] = v.w;
    }
    __syncthreads();
    const int kp = tid & 31;
    const int nb = tid >> 5;
#pragma unroll
    for (int ph = 0; ph < 8; ph++) {
        int n = nb + ph * 8;
        WT[(size_t)(n0 + n) * KP_TOT + (k0 >> 1) + kp] =
            packh(sm[2 * kp][n], sm[2 * kp + 1][n]);
    }
}

// ---------------------------------------------------------------------------
// fp16 tensor-core GEMM tile — ldmatrix fragment loads (round-16 validated)
// ---------------------------------------------------------------------------
#define FSTR 36

__device__ __forceinline__ void gemm_fp16_tile(
    const uint32_t* __restrict__ Ap, const uint32_t* __restrict__ Bp,
    float* __restrict__ C, int ldc, int m0, int n0)
{
    __shared__ uint32_t As[128][FSTR];
    __shared__ uint32_t Bs[128][FSTR];

    const int tid  = threadIdx.x;
    const int lane = tid & 31;
    const int wid  = tid >> 5;
    const int wm   = wid >> 2;
    const int wn   = wid & 3;
    const int g    = lane >> 2;
    const int t    = lane & 3;

    const int aRow = (lane & 7) + ((lane >> 3) & 1) * 8;
    const int aCol = (lane >> 4) * 4;
    const int bRow = (lane & 7) + ((lane >> 4) & 1) * 8;
    const int bCol = ((lane >> 3) & 1) * 4;

    const uint32_t sAu = (uint32_t)__cvta_generic_to_shared(&As[0][0]);
    const uint32_t sBu = (uint32_t)__cvta_generic_to_shared(&Bs[0][0]);

    float acc[4][4][4];
#pragma unroll
    for (int mm = 0; mm < 4; mm++)
#pragma unroll
        for (int nn = 0; nn < 4; nn++)
#pragma unroll
            for (int i = 0; i < 4; i++) acc[mm][nn][i] = 0.0f;

    uint4 pa[2], pb[2];
#pragma unroll
    for (int i = 0; i < 2; i++) {
        int idx = tid + i * 256;
        int r = idx >> 2, u = idx & 3;
        pa[i] = *(const uint4*)&Ap[(size_t)(m0 + r) * KP_TOT + u * 4];
        pb[i] = *(const uint4*)&Bp[(size_t)(n0 + r) * KP_TOT + u * 4];
    }

    for (int kt = 0; kt < 64; kt++) {
#pragma unroll
        for (int i = 0; i < 2; i++) {
            int idx = tid + i * 256;
            int r = idx >> 2, u = idx & 3;
            *(uint4*)&As[r][u * 4] = pa[i];
            *(uint4*)&Bs[r][u * 4] = pb[i];
        }
        __syncthreads();

        if (kt + 1 < 64) {
#pragma unroll
            for (int i = 0; i < 2; i++) {
                int idx = tid + i * 256;
                int r = idx >> 2, u = idx & 3;
                pa[i] = *(const uint4*)&Ap[(size_t)(m0 + r) * KP_TOT + (kt + 1) * 16 + u * 4];
                pb[i] = *(const uint4*)&Bp[(size_t)(n0 + r) * KP_TOT + (kt + 1) * 16 + u * 4];
            }
        }

#pragma unroll
        for (int ks = 0; ks < 2; ks++) {
            const int ko = ks * 8;
            uint32_t af[4][4], bf2[4][2];
#pragma unroll
            for (int mm = 0; mm < 4; mm++) {
                uint32_t addr = sAu +
                    (((wm * 64 + mm * 16 + aRow) * FSTR) + ko + aCol) * 4;
                ldsm4(af[mm][0], af[mm][1], af[mm][2], af[mm][3], addr);
            }
#pragma unroll
            for (int nn = 0; nn < 4; nn += 2) {
                uint32_t addr = sBu +
                    (((wn * 32 + nn * 8 + bRow) * FSTR) + ko + bCol) * 4;
                ldsm4(bf2[nn][0], bf2[nn][1], bf2[nn + 1][0], bf2[nn + 1][1], addr);
            }
#pragma unroll
            for (int mm = 0; mm < 4; mm++)
#pragma unroll
                for (int nn = 0; nn < 4; nn++)
                    mma_fp16(acc[mm][nn], af[mm][0], af[mm][1], af[mm][2], af[mm][3],
                             bf2[nn][0], bf2[nn][1]);
        }
        __syncthreads();
    }

#pragma unroll
    for (int mm = 0; mm < 4; mm++)
#pragma unroll
        for (int nn = 0; nn < 4; nn++) {
            int row = m0 + wm * 64 + mm * 16 + g;
            int col = n0 + wn * 32 + nn * 8 + t * 2;
            *(float2*)&C[(size_t)row * ldc + col] =
                make_float2(acc[mm][nn][0], acc[mm][nn][1]);
            *(float2*)&C[(size_t)(row + 8) * ldc + col] =
                make_float2(acc[mm][nn][2], acc[mm][nn][3]);
        }
}

__global__ void __launch_bounds__(256) qkv_fp16()
{
    int ncol0 = blockIdx.x * 128;
    int m0    = blockIdx.y * 128;
    const uint32_t* Bp;
    float* Cp;
    int ldc, n0;
    if (ncol0 < 2048)      { Bp = g_WqT; Cp = g_q; ldc = QW; n0 = ncol0;        }
    else if (ncol0 < 2560) { Bp = g_WkT; Cp = g_k; ldc = KW; n0 = ncol0 - 2048; }
    else                   { Bp = g_WvT; Cp = g_v; ldc = KW; n0 = ncol0 - 2560; }
    gemm_fp16_tile(g_xP, Bp, Cp, ldc, m0, n0);
}

__global__ void __launch_bounds__(256) out_fp16(float* __restrict__ out)
{
    gemm_fp16_tile((const uint32_t*)g_oP, g_WoT, out, DMODEL,
                   blockIdx.y * 128, blockIdx.x * 128);
}

// ---------------------------------------------------------------------------
// RoPE (validated negated angle)
// ---------------------------------------------------------------------------
__global__ void __launch_bounds__(256) rope_kernel(int which)
{
    float* p     = which ? g_k : g_q;
    const int nh = which ? NKV : NH;
    int idx  = blockIdx.x * 256 + threadIdx.x;
    int dd   = idx & 63;
    int rest = idx >> 6;
    int head = rest & (nh - 1);
    int row  = rest / nh;
    if (row >= SB) return;
    int s = row >> 1;

    float e    = (float)(2 * dd) / 128.0f;
    float invf = 1.0f / powf(10000.0f, e);
    float ang  = -(float)s * invf;
    float c, sn;
    sincosf(ang, &c, &sn);

    float* base = p + (size_t)row * (nh * HD) + head * HD;
    float u1 = base[dd];
    float u2 = base[dd + 64];
    base[dd]      = u1 * c - u2 * sn;
    base[dd + 64] = u2 * c + u1 * sn;
}

// ---------------------------------------------------------------------------
// Flash attention v6: v5 + ldmatrix fragment loads for QK and PV.
// ---------------------------------------------------------------------------
#define BSTR 68      // Q/K bf16-pair row stride (words)
#define VST  36      // V fp16-pair row stride (words), [d][jpair]
#define PST  36      // P fp16-pair row stride (words), [row][jpair]

__global__ void __launch_bounds__(256, 1) flash_tc()
{
    extern __shared__ uint32_t smu[];
    uint32_t* sQh = smu;                      // [128][BSTR]
    uint32_t* sQl = sQh + 128 * BSTR;         // [128][BSTR]
    uint32_t* sKh = sQl + 128 * BSTR;         // [64][BSTR]
    uint32_t* sKl = sKh + 64 * BSTR;          // [64][BSTR]
    uint32_t* sVp = sKl + 64 * BSTR;          // [128 d][VST] fp16x2 pairs along j
    uint32_t* sP  = sVp + 128 * VST;          // [8][16][PST] fp16x2 pairs along j

    const int qt  = 15 - blockIdx.x;
    const int bh  = blockIdx.y;
    const int b   = bh >> 4;
    const int h   = bh & 15;
    const int kvh = h >> 2;
    const int tid  = threadIdx.x;
    const int lane = tid & 31;
    const int w    = tid >> 5;
    const int g    = lane >> 2;
    const int t    = lane & 3;

    const int aRow = (lane & 7) + ((lane >> 3) & 1) * 8;
    const int aCol = (lane >> 4) * 4;
    const int bRow = (lane & 7) + ((lane >> 4) & 1) * 8;
    const int bCol = ((lane >> 3) & 1) * 4;

    const uint32_t uQh = (uint32_t)__cvta_generic_to_shared(sQh);
    const uint32_t uQl = (uint32_t)__cvta_generic_to_shared(sQl);
    const uint32_t uKh = (uint32_t)__cvta_generic_to_shared(sKh);
    const uint32_t uKl = (uint32_t)__cvta_generic_to_shared(sKl);
    const uint32_t uV  = (uint32_t)__cvta_generic_to_shared(sVp);
    const uint32_t uP  = (uint32_t)__cvta_generic_to_shared(sP) + (w * 16 * PST) * 4;

    // Load + split + pack Q tile (128 x 128)
    for (int idx = tid; idx < 128 * 32; idx += 256) {
        int r  = idx >> 5;
        int c4 = (idx & 31) << 2;
        float4 q = *(const float4*)&g_q[((size_t)(qt * 128 + r) * BATCH + b) * QW + h * HD + c4];
        __nv_bfloat16 xh, xl, yh, yl, zh, zl, wh, wl;
        splitb(q.x, xh, xl); splitb(q.y, yh, yl);
        splitb(q.z, zh, zl); splitb(q.w, wh, wl);
        int p0 = r * BSTR + (c4 >> 1);
        sQh[p0]     = packb(xh, yh);
        sQh[p0 + 1] = packb(zh, wh);
        sQl[p0]     = packb(xl, yl);
        sQl[p0 + 1] = packb(zl, wl);
    }

    float oacc[16][4];
#pragma unroll
    for (int dt = 0; dt < 16; dt++)
#pragma unroll
        for (int i = 0; i < 4; i++) oacc[dt][i] = 0.0f;
    float m0 = -1e30f, m1 = -1e30f, l0 = 0.0f, l1 = 0.0f;

    const float sc = 0.08838834764831845f;
    const int r0 = qt * 128 + w * 16 + g;
    const int r1 = r0 + 8;
    uint32_t* pw = sP + w * 16 * PST;

    const int nkt = 2 * qt + 2;

    float4 pk[8], pva[4], pvb[4];
#pragma unroll
    for (int i = 0; i < 8; i++) {
        int idx = tid + i * 256;
        int j  = idx >> 5;
        int c4 = (idx & 31) << 2;
        pk[i] = *(const float4*)&g_k[((size_t)j * BATCH + b) * KW + kvh * HD + c4];
    }
#pragma unroll
    for (int it = 0; it < 4; it++) {
        int d0 = w * 16 + it * 4;
        size_t ga = ((size_t)(2 * lane) * BATCH + b) * KW + kvh * HD + d0;
        pva[it] = *(const float4*)&g_v[ga];
        pvb[it] = *(const float4*)&g_v[ga + (size_t)BATCH * KW];
    }

    for (int kt = 0; kt < nkt; kt++) {
        __syncthreads();
#pragma unroll
        for (int i = 0; i < 8; i++) {
            int idx = tid + i * 256;
            int j  = idx >> 5;
            int c4 = (idx & 31) << 2;
            __nv_bfloat16 xh, xl, yh, yl, zh, zl, wh, wl;
            splitb(pk[i].x, xh, xl); splitb(pk[i].y, yh, yl);
            splitb(pk[i].z, zh, zl); splitb(pk[i].w, wh, wl);
            int p0 = j * BSTR + (c4 >> 1);
            sKh[p0]     = packb(xh, yh);
            sKh[p0 + 1] = packb(zh, wh);
            sKl[p0]     = packb(xl, yl);
            sKl[p0 + 1] = packb(zl, wl);
        }
#pragma unroll
        for (int it = 0; it < 4; it++) {
            int d0 = w * 16 + it * 4;
            sVp[(d0 + 0) * VST + lane] = packh(pva[it].x, pvb[it].x);
            sVp[(d0 + 1) * VST + lane] = packh(pva[it].y, pvb[it].y);
            sVp[(d0 + 2) * VST + lane] = packh(pva[it].z, pvb[it].z);
            sVp[(d0 + 3) * VST + lane] = packh(pva[it].w, pvb[it].w);
        }
        __syncthreads();

        if (kt + 1 < nkt) {
#pragma unroll
            for (int i = 0; i < 8; i++) {
                int idx = tid + i * 256;
                int j  = idx >> 5;
                int c4 = (idx & 31) << 2;
                pk[i] = *(const float4*)&g_k[((size_t)((kt + 1) * 64 + j) * BATCH + b) * KW + kvh * HD + c4];
            }
#pragma unroll
            for (int it = 0; it < 4; it++) {
                int d0 = w * 16 + it * 4;
                size_t ga = ((size_t)((kt + 1) * 64 + 2 * lane) * BATCH + b) * KW + kvh * HD + d0;
                pva[it] = *(const float4*)&g_v[ga];
                pvb[it] = *(const float4*)&g_v[ga + (size_t)BATCH * KW];
            }
        }

        if (kt * 64 <= qt * 128 + w * 16 + 15) {
            // ---- scores: split-bf16 3-term, ldmatrix frag loads ----
            float sacc[8][4];
#pragma unroll
            for (int nt = 0; nt < 8; nt++)
#pragma unroll
                for (int i = 0; i < 4; i++) sacc[nt][i] = 0.0f;

#pragma unroll
            for (int ks = 0; ks < 8; ks++) {
                uint32_t ah0, ah1, ah2, ah3, al0, al1, al2, al3;
                uint32_t qaddr = ((w * 16 + aRow) * BSTR + ks * 8 + aCol) * 4;
                ldsm4(ah0, ah1, ah2, ah3, uQh + qaddr);
                ldsm4(al0, al1, al2, al3, uQl + qaddr);
#pragma unroll
                for (int np = 0; np < 4; np++) {
                    uint32_t kaddr = ((np * 16 + bRow) * BSTR + ks * 8 + bCol) * 4;
                    uint32_t kh0, kh1, kh2, kh3, kl0, kl1, kl2, kl3;
                    ldsm4(kh0, kh1, kh2, kh3, uKh + kaddr);
                    ldsm4(kl0, kl1, kl2, kl3, uKl + kaddr);
                    mma_bf16(sacc[2*np],   ah0, ah1, ah2, ah3, kh0, kh1);
                    mma_bf16(sacc[2*np],   ah0, ah1, ah2, ah3, kl0, kl1);
                    mma_bf16(sacc[2*np],   al0, al1, al2, al3, kh0, kh1);
                    mma_bf16(sacc[2*np+1], ah0, ah1, ah2, ah3, kh2, kh3);
                    mma_bf16(sacc[2*np+1], ah0, ah1, ah2, ah3, kl2, kl3);
                    mma_bf16(sacc[2*np+1], al0, al1, al2, al3, kh2, kh3);
                }
            }

            // ---- scale + mask + online softmax ----
            const bool need_mask = (kt >= 2 * qt);
            float mx0 = -1e30f, mx1 = -1e30f;
#pragma unroll
            for (int nt = 0; nt < 8; nt++) {
                int c0 = kt * 64 + nt * 8 + 2 * t;
#pragma unroll
                for (int i = 0; i < 4; i++) {
                    float v = sacc[nt][i] * sc;
                    if (need_mask) {
                        int col = c0 + (i & 1);
                        int row = (i < 2) ? r0 : r1;
                        if (col > row) v = -1e30f;
                    }
                    sacc[nt][i] = v;
                }
                mx0 = fmaxf(mx0, fmaxf(sacc[nt][0], sacc[nt][1]));
                mx1 = fmaxf(mx1, fmaxf(sacc[nt][2], sacc[nt][3]));
            }
#pragma unroll
            for (int off = 1; off <= 2; off <<= 1) {
                mx0 = fmaxf(mx0, __shfl_xor_sync(0xffffffffu, mx0, off));
                mx1 = fmaxf(mx1, __shfl_xor_sync(0xffffffffu, mx1, off));
            }
            float mn0 = fmaxf(m0, mx0), mn1 = fmaxf(m1, mx1);
            float corr0 = expf(m0 - mn0), corr1 = expf(m1 - mn1);
            m0 = mn0; m1 = mn1;

            float sum0 = 0.0f, sum1 = 0.0f;
#pragma unroll
            for (int nt = 0; nt < 8; nt++) {
                float p00 = expf(sacc[nt][0] - m0);
                float p01 = expf(sacc[nt][1] - m0);
                float p10 = expf(sacc[nt][2] - m1);
                float p11 = expf(sacc[nt][3] - m1);
                sum0 += p00 + p01;
                sum1 += p10 + p11;
                pw[g * PST + nt * 4 + t]       = packh(p00, p01);
                pw[(g + 8) * PST + nt * 4 + t] = packh(p10, p11);
            }
#pragma unroll
            for (int off = 1; off <= 2; off <<= 1) {
                sum0 += __shfl_xor_sync(0xffffffffu, sum0, off);
                sum1 += __shfl_xor_sync(0xffffffffu, sum1, off);
            }
            l0 = l0 * corr0 + sum0;
            l1 = l1 * corr1 + sum1;
#pragma unroll
            for (int dt = 0; dt < 16; dt++) {
                oacc[dt][0] *= corr0; oacc[dt][1] *= corr0;
                oacc[dt][2] *= corr1; oacc[dt][3] *= corr1;
            }
            __syncwarp();

            // ---- O += P @ V, fp16 k16, ldmatrix frag loads ----
#pragma unroll
            for (int ks = 0; ks < 4; ks++) {
                uint32_t a0, a1, a2, a3;
                ldsm4(a0, a1, a2, a3, uP + (aRow * PST + ks * 8 + aCol) * 4);
#pragma unroll
                for (int dp = 0; dp < 8; dp++) {
                    uint32_t v0, v1, v2, v3;
                    ldsm4(v0, v1, v2, v3,
                          uV + ((dp * 16 + bRow) * VST + ks * 8 + bCol) * 4);
                    mma_fp16(oacc[2*dp],   a0, a1, a2, a3, v0, v1);
                    mma_fp16(oacc[2*dp+1], a0, a1, a2, a3, v2, v3);
                }
            }
        }
    }

    // ---- epilogue: write fp16-packed O directly ----
    float invl0 = 1.0f / l0, invl1 = 1.0f / l1;
    const size_t row0 = (size_t)r0 * BATCH + b;
    const size_t row1 = (size_t)r1 * BATCH + b;
#pragma unroll
    for (int dt = 0; dt < 16; dt++) {
        int kp = h * 64 + dt * 4 + t;
        g_oP[row0 * KP_TOT + kp] = packh(oacc[dt][0] * invl0, oacc[dt][1] * invl0);
        g_oP[row1 * KP_TOT + kp] = packh(oacc[dt][2] * invl1, oacc[dt][3] * invl1);
    }
}

// ---------------------------------------------------------------------------
// Launch
// ---------------------------------------------------------------------------
extern "C" void kernel_launch(void* const* d_in, const int* in_sizes, int n_in,
                              void* d_out, int out_size)
{
    int ix = -1, ik = -1, iv = -1, ia = -1, ib = -1;
    for (int i = 0; i < n_in; i++) {
        if (in_sizes[i] == 8388608) { ix = i; }
        else if (in_sizes[i] == 1048576) { if (ik < 0) ik = i; else iv = i; }
        else if (in_sizes[i] == 4194304) { if (ia < 0) ia = i; else ib = i; }
    }
    int iq, io;
    if (ix == 0) { iq = ia; io = ib; }
    else         { io = ia; iq = ib; }

    const float* x  = (const float*)d_in[ix];
    const float* Wq = (const float*)d_in[iq];
    const float* Wk = (const float*)d_in[ik];
    const float* Wv = (const float*)d_in[iv];
    const float* Wo = (const float*)d_in[io];
    float* out = (float*)d_out;

    uint32_t* xP;  cudaGetSymbolAddress((void**)&xP,  g_xP);
    uint32_t* WqT; cudaGetSymbolAddress((void**)&WqT, g_WqT);
    uint32_t* WkT; cudaGetSymbolAddress((void**)&WkT, g_WkT);
    uint32_t* WvT; cudaGetSymbolAddress((void**)&WvT, g_WvT);
    uint32_t* WoT; cudaGetSymbolAddress((void**)&WoT, g_WoT);

    const int N4 = SB * DMODEL / 4;
    pack_h2<<<(N4 + 255) / 256, 256>>>(x, xP, N4);
    transpose_pack<<<dim3(32, 32), 256>>>(Wq, WqT, 2048);
    transpose_pack<<<dim3( 8, 32), 256>>>(Wk, WkT,  512);
    transpose_pack<<<dim3( 8, 32), 256>>>(Wv, WvT,  512);
    transpose_pack<<<dim3(32, 32), 256>>>(Wo, WoT, 2048);

    qkv_fp16<<<dim3(24, 32), 256>>>();

    rope_kernel<<<(SB * NH  * 64) / 256, 256>>>(0);
    rope_kernel<<<(SB * NKV * 64) / 256, 256>>>(1);

    const int FLASH_SMEM =
        (2 * 128 * BSTR + 2 * 64 * BSTR + 128 * VST + 8 * 16 * PST) * (int)sizeof(uint32_t);
    cudaFuncSetAttribute(flash_tc, cudaFuncAttributeMaxDynamicSharedMemorySize, FLASH_SMEM);
    flash_tc<<<dim3(16, 32), 256, FLASH_SMEM>>>();

    out_fp16<<<dim3(16, 32), 256>>>(out);
}